// round 5
// baseline (speedup 1.0000x reference)
#include <cuda_runtime.h>
#include <math.h>
#include <float.h>

// LSH attention: B=16, S=4096, D=64, H=8 hashes, bucket_size=64
#define BB 16
#define SS 4096
#define DD 64
#define HH 8
#define NBK 64          // n_buckets
#define CPB 512         // chunks per batch = H * n_buckets
#define TILES_PER_B 64  // S / 64

typedef unsigned long long u64;

// ---------------- scratch (device globals; no allocation allowed) ----------------
__device__ unsigned char g_bucket[BB * HH * SS];          // 512 KB
__device__ int           g_st[BB * HH * SS];              // 2 MB  sorted original positions
__device__ float         g_norm[BB * SS];                 // 256 KB
__device__ float         g_logits[BB * HH * SS];          // 2 MB
__device__ float         g_o[(size_t)BB * HH * SS * DD];  // 134 MB

// packed f32x2 FMA (SASS FFMA2) — used only where reduction order doesn't
// feed a discrete decision (attention dots -> smooth softmax).
__device__ __forceinline__ void ffma2(u64 &acc, u64 a, u64 b) {
    asm volatile("fma.rn.f32x2 %0, %1, %2, %0;" : "+l"(acc) : "l"(a), "l"(b));
}
__device__ __forceinline__ float fsum2(u64 x) {
    float lo = __uint_as_float((unsigned)(x & 0xffffffffu));
    float hi = __uint_as_float((unsigned)(x >> 32));
    return lo + hi;
}

// =====================================================================
// Kernel 1: hash projection + argmax buckets + token norms
//   rotated[b,h,t,i] = sum_f qk[b,t,f] * rot[f,h,i]
// Accumulation: ONE accumulator per output, scalar fp32 FMA, f ascending
// 0..63 (canonical cuBLAS/CUTLASS order) so rounding matches the
// reference GEMM and argmax never flips.
// qs reads use float2 ONLY: row stride 66 floats = 264 B is 8B-aligned
// for every row but NOT 16B-aligned for odd rows (float4 traps).
// =====================================================================
__global__ void __launch_bounds__(512) k_hash(const float* __restrict__ qk,
                                              const float* __restrict__ rot) {
    extern __shared__ float sm1[];
    float* qs   = sm1;                 // 64 x 66  (8B-aligned rows)
    float* rotT = sm1 + 64 * 66;       // 256 x 68 (16B-aligned rows)
    float* rt   = rotT + 256 * 68;     // 64 x 258 (rotated outputs)

    int tid = threadIdx.x;
    int b   = blockIdx.x >> 6;
    int tb  = (blockIdx.x & 63) * 64;

    for (int i = tid; i < 64 * 64; i += 512) {
        int r = i >> 6, f = i & 63;
        qs[r * 66 + f] = qk[((size_t)(b * SS + tb + r)) * DD + f];
    }
    // rot layout: (1, D, H, 32) -> idx = f*256 + (h*32+i) = f*256 + c
    for (int i = tid; i < 64 * 256; i += 512) {
        int f = i >> 8, c = i & 255;
        rotT[c * 68 + f] = rot[i];
    }
    __syncthreads();

    if (tid < 64) {
        float ssq = 0.f;
        #pragma unroll 8
        for (int f = 0; f < 64; f++) { float x = qs[tid * 66 + f]; ssq += x * x; }
        g_norm[b * SS + tb + tid] = sqrtf(ssq);
    }

    {
        int w = tid >> 5, lane = tid & 31;
        int c0 = w * 16;
        #pragma unroll
        for (int tg = 0; tg < 2; tg++) {
            int tok = tg * 32 + lane;
            float acc[16];
            #pragma unroll
            for (int j = 0; j < 16; j++) acc[j] = 0.f;

            for (int fc = 0; fc < 64; fc += 8) {
                // float2 loads: 8B alignment holds for all rows (264*tok + 4*fc, fc%4==0)
                float2 qa = *(const float2*)&qs[tok * 66 + fc];
                float2 qb = *(const float2*)&qs[tok * 66 + fc + 2];
                float2 qc = *(const float2*)&qs[tok * 66 + fc + 4];
                float2 qd = *(const float2*)&qs[tok * 66 + fc + 6];
                float qv0 = qa.x, qv1 = qa.y, qv2 = qb.x, qv3 = qb.y;
                float qv4 = qc.x, qv5 = qc.y, qv6 = qd.x, qv7 = qd.y;
                #pragma unroll
                for (int j = 0; j < 16; j++) {
                    const float4* rp = (const float4*)&rotT[(c0 + j) * 68 + fc];
                    float4 r0 = rp[0];
                    float4 r1 = rp[1];
                    // strict ascending-f dependent chain, single accumulator
                    float a = acc[j];
                    a = __fmaf_rn(qv0, r0.x, a);
                    a = __fmaf_rn(qv1, r0.y, a);
                    a = __fmaf_rn(qv2, r0.z, a);
                    a = __fmaf_rn(qv3, r0.w, a);
                    a = __fmaf_rn(qv4, r1.x, a);
                    a = __fmaf_rn(qv5, r1.y, a);
                    a = __fmaf_rn(qv6, r1.z, a);
                    a = __fmaf_rn(qv7, r1.w, a);
                    acc[j] = a;
                }
            }
            #pragma unroll
            for (int j = 0; j < 16; j++)
                rt[tok * 258 + c0 + j] = acc[j];
        }
    }
    __syncthreads();

    // argmax over concat [r, -r] per (token, h): 512 tasks, one per thread
    // (first-occurrence tie semantics, matching jnp.argmax)
    {
        int tok = tid >> 3, h = tid & 7;
        const float* p = &rt[tok * 258 + h * 32];
        float best = p[0]; int bi = 0;
        #pragma unroll 4
        for (int i = 1; i < 32; i++) { float v = p[i];  if (v > best) { best = v; bi = i; } }
        #pragma unroll 4
        for (int i = 0; i < 32; i++) { float v = -p[i]; if (v > best) { best = v; bi = 32 + i; } }
        g_bucket[(size_t)(b * HH + h) * SS + tb + tok] = (unsigned char)bi;
    }
}

// =====================================================================
// Kernel 2: stable counting sort per (b,h) by (bucket, position)
// =====================================================================
__global__ void __launch_bounds__(256) k_sort() {
    __shared__ unsigned char bk[SS];
    __shared__ int cnt[64];
    __shared__ int off[64];
    int tid = threadIdx.x;
    int b = blockIdx.x >> 3, h = blockIdx.x & 7;
    size_t base = (size_t)(b * HH + h) * SS;

    if (tid < 64) cnt[tid] = 0;
    __syncthreads();
    for (int t = tid; t < SS; t += 256) {
        unsigned char bb = g_bucket[base + t];
        bk[t] = bb;
        atomicAdd(&cnt[bb], 1);
    }
    __syncthreads();
    if (tid == 0) {
        int run = 0;
        for (int j = 0; j < 64; j++) { off[j] = run; run += cnt[j]; }
    }
    __syncthreads();
    if (tid < 64) {
        int p = off[tid];
        unsigned char me = (unsigned char)tid;
        for (int t = 0; t < SS; t++) {
            if (bk[t] == me) g_st[base + p++] = t;
        }
    }
}

// =====================================================================
// Kernel 3: chunked attention. One block per (b, chunk). 256 threads.
//   kv = [chunk c, chunk c-1 (wrap over full 512-chunk axis)]
//   dots = q @ k_norm^T / 8; causal + self masks; softmax w/ lse;
//   out = attn @ v ; scatter to g_o / g_logits by original token pos.
// Uses q_i = norm_i * k_i  => only normalized K stored; dots scaled by row.
// All u64 (f32x2) shared loads are 8B-aligned: row strides 66/130 floats
// = 264/520 bytes, both multiples of 8; f,j offsets always even.
// =====================================================================
__global__ void __launch_bounds__(256, 2) k_attn(const float* __restrict__ qk,
                                                 const float* __restrict__ v) {
    extern __shared__ float sm3[];
    float* ks   = sm3;                  // 128 x 66  (normalized rows)
    float* vT   = ks + 128 * 66;        // 64 x 130  (v transposed: [d][j])
    float* dots = vT + 64 * 130;        // 64 x 130

    __shared__ int   tkv[128];
    __shared__ float sQ[64];            // max(norm, 1e-12) for the 64 q rows

    int tid = threadIdx.x;
    int b = blockIdx.x >> 9;
    int c = blockIdx.x & 511;
    int cp = (c + CPB - 1) & (CPB - 1);
    int h = c >> 6, hp = cp >> 6;
    size_t baseq = (size_t)(b * HH + h)  * SS + (c  & 63) * 64;
    size_t basep = (size_t)(b * HH + hp) * SS + (cp & 63) * 64;

    if (tid < 64) {
        int t = g_st[baseq + tid];
        tkv[tid] = t;
        sQ[tid] = fmaxf(g_norm[b * SS + t], 1e-12f);
    } else if (tid < 128) {
        tkv[tid] = g_st[basep + tid - 64];
    }
    __syncthreads();

    // gather K (normalized) and V (transposed): 128 rows x 16 float4
    for (int i = tid; i < 128 * 16; i += 256) {
        int j = i >> 4, q4 = i & 15;
        int t = tkv[j];
        size_t rowoff = ((size_t)b * SS + t) * DD + q4 * 4;
        float4 kq = *(const float4*)(qk + rowoff);
        float rn = 1.0f / fmaxf(g_norm[b * SS + t], 1e-12f);
        float* kd = &ks[j * 66 + q4 * 4];
        kd[0] = kq.x * rn; kd[1] = kq.y * rn; kd[2] = kq.z * rn; kd[3] = kq.w * rn;
        float4 vv = *(const float4*)(v + rowoff);
        int d0 = q4 * 4;
        vT[(d0 + 0) * 130 + j] = vv.x;
        vT[(d0 + 1) * 130 + j] = vv.y;
        vT[(d0 + 2) * 130 + j] = vv.z;
        vT[(d0 + 3) * 130 + j] = vv.w;
    }
    __syncthreads();

    int ty = tid >> 5, tx = tid & 31;

    // GEMM1: G[i][j] = k_i . k_j  (i<64 rows, j<128), 8x4 tile per thread
    {
        u64 acc[8][4];
        #pragma unroll
        for (int rr = 0; rr < 8; rr++)
            #pragma unroll
            for (int jj = 0; jj < 4; jj++) acc[rr][jj] = 0ull;

        for (int f = 0; f < 64; f += 2) {
            u64 qv[8], kv2[4];
            #pragma unroll
            for (int rr = 0; rr < 8; rr++)
                qv[rr] = *(const u64*)&ks[(ty * 8 + rr) * 66 + f];
            #pragma unroll
            for (int jj = 0; jj < 4; jj++)
                kv2[jj] = *(const u64*)&ks[(tx + 32 * jj) * 66 + f];
            #pragma unroll
            for (int rr = 0; rr < 8; rr++)
                #pragma unroll
                for (int jj = 0; jj < 4; jj++)
                    ffma2(acc[rr][jj], qv[rr], kv2[jj]);
        }
        #pragma unroll
        for (int rr = 0; rr < 8; rr++) {
            int row = ty * 8 + rr;
            int tq  = tkv[row];
            float s = sQ[row] * 0.125f;   // norm_i * D^-0.5
            #pragma unroll
            for (int jj = 0; jj < 4; jj++) {
                int col = tx + 32 * jj;
                int tk  = tkv[col];
                float val = fsum2(acc[rr][jj]) * s;
                if (tq < tk)  val = -3.402823466e38f;   // causal mask
                if (tq == tk) val = -50000.0f;          // self mask
                dots[row * 130 + col] = val;
            }
        }
    }
    __syncthreads();

    // softmax per row (warp ty handles rows ty*8..ty*8+7), write lse/logits
    for (int rr = 0; rr < 8; rr++) {
        int row = ty * 8 + rr;
        float v0 = dots[row * 130 + tx];
        float v1 = dots[row * 130 + tx + 32];
        float v2 = dots[row * 130 + tx + 64];
        float v3 = dots[row * 130 + tx + 96];
        float m = fmaxf(fmaxf(v0, v1), fmaxf(v2, v3));
        #pragma unroll
        for (int o = 16; o > 0; o >>= 1) m = fmaxf(m, __shfl_xor_sync(0xffffffffu, m, o));
        float e0 = expf(v0 - m), e1 = expf(v1 - m), e2 = expf(v2 - m), e3 = expf(v3 - m);
        float sum = e0 + e1 + e2 + e3;
        #pragma unroll
        for (int o = 16; o > 0; o >>= 1) sum += __shfl_xor_sync(0xffffffffu, sum, o);
        float inv = 1.0f / sum;
        dots[row * 130 + tx]      = e0 * inv;
        dots[row * 130 + tx + 32] = e1 * inv;
        dots[row * 130 + tx + 64] = e2 * inv;
        dots[row * 130 + tx + 96] = e3 * inv;
        if (tx == 0)
            g_logits[(size_t)(b * HH + h) * SS + tkv[row]] = m + logf(sum);
    }
    __syncthreads();

    // GEMM2: out[i][d] = sum_j attn[i][j] * vT[d][j]; 8x2 tile per thread
    {
        u64 acc[8][2];
        #pragma unroll
        for (int rr = 0; rr < 8; rr++) { acc[rr][0] = 0ull; acc[rr][1] = 0ull; }

        for (int j = 0; j < 128; j += 2) {
            u64 av[8];
            #pragma unroll
            for (int rr = 0; rr < 8; rr++)
                av[rr] = *(const u64*)&dots[(ty * 8 + rr) * 130 + j];
            u64 w0 = *(const u64*)&vT[tx * 130 + j];
            u64 w1 = *(const u64*)&vT[(tx + 32) * 130 + j];
            #pragma unroll
            for (int rr = 0; rr < 8; rr++) {
                ffma2(acc[rr][0], av[rr], w0);
                ffma2(acc[rr][1], av[rr], w1);
            }
        }
        #pragma unroll
        for (int rr = 0; rr < 8; rr++) {
            int row = ty * 8 + rr;
            int t = tkv[row];
            float* dst = &g_o[((size_t)(b * HH + h) * SS + t) * DD];
            dst[tx]      = fsum2(acc[rr][0]);
            dst[tx + 32] = fsum2(acc[rr][1]);
        }
    }
}

// =====================================================================
// Kernel 4: combine hash rounds via softmax over per-hash logits
// =====================================================================
__global__ void __launch_bounds__(256) k_combine(float* __restrict__ out) {
    int gid = blockIdx.x * 256 + threadIdx.x;   // B*S*4 total
    int token = gid >> 2, q = gid & 3;
    int b = token >> 12, t = token & 4095;

    float l[HH];
    #pragma unroll
    for (int h = 0; h < HH; h++)
        l[h] = g_logits[(size_t)(b * HH + h) * SS + t];
    float m = l[0];
    #pragma unroll
    for (int h = 1; h < HH; h++) m = fmaxf(m, l[h]);
    float w[HH]; float sum = 0.f;
    #pragma unroll
    for (int h = 0; h < HH; h++) { w[h] = expf(l[h] - m); sum += w[h]; }
    float inv = 1.0f / sum;

    float4 acc[4];
    #pragma unroll
    for (int k = 0; k < 4; k++) acc[k] = make_float4(0.f, 0.f, 0.f, 0.f);
    #pragma unroll
    for (int h = 0; h < HH; h++) {
        const float4* src =
            (const float4*)&g_o[((size_t)(b * HH + h) * SS + t) * DD + q * 16];
        float wh = w[h] * inv;
        #pragma unroll
        for (int k = 0; k < 4; k++) {
            float4 x = src[k];
            acc[k].x += x.x * wh; acc[k].y += x.y * wh;
            acc[k].z += x.z * wh; acc[k].w += x.w * wh;
        }
    }
    float4* dst = (float4*)(out + ((size_t)b * SS + t) * DD + q * 16);
    #pragma unroll
    for (int k = 0; k < 4; k++) dst[k] = acc[k];
}

// =====================================================================
extern "C" void kernel_launch(void* const* d_in, const int* in_sizes, int n_in,
                              void* d_out, int out_size) {
    const float* qk  = (const float*)d_in[0];
    const float* v   = (const float*)d_in[1];
    const float* rot = (const float*)d_in[2];
    float* out = (float*)d_out;

    const int smem1 = (64 * 66 + 256 * 68 + 64 * 258) * 4;   // 152576 B
    const int smem3 = (128 * 66 + 64 * 130 + 64 * 130) * 4;  // 100352 B
    cudaFuncSetAttribute(k_hash, cudaFuncAttributeMaxDynamicSharedMemorySize, smem1);
    cudaFuncSetAttribute(k_attn, cudaFuncAttributeMaxDynamicSharedMemorySize, smem3);

    k_hash<<<BB * TILES_PER_B, 512, smem1>>>(qk, rot);
    k_sort<<<BB * HH, 256>>>();
    k_attn<<<BB * CPB, 256, smem3>>>(qk, v);
    k_combine<<<BB * SS * 4 / 256, 256>>>(out);
}